// round 10
// baseline (speedup 1.0000x reference)
#include <cuda_runtime.h>
#include <math.h>

#define BATCH   64
#define IN_F    512
#define OUT_F   512

// Scratch (no allocations allowed -> __device__ globals)
__device__ float gScale[OUT_F];            // exp(diag_w)*rsqrt(wsn) per row
__device__ float gPart[8 * BATCH * OUT_F]; // out partials [kc][b][r], kc<=rt only

// triangular (rt,kc) enumeration for the 36 non-zero out tiles
__device__ const int RT_[36] = {0,1,1,2,2,2,3,3,3,3,4,4,4,4,4,5,5,5,5,5,5,
                                6,6,6,6,6,6,6,7,7,7,7,7,7,7,7};
__device__ const int KC_[36] = {0,0,1,0,1,2,0,1,2,3,0,1,2,3,4,0,1,2,3,4,5,
                                0,1,2,3,4,5,6,0,1,2,3,4,5,6,7};

// ---------------------------------------------------------------------------
// K1: row norms only.  One CTA (128 thr) per row; warp w covers cols
//     [w*128,(w+1)*128) -- skipped entirely if above the diag block.
//     u = exp(W) on diag / W below / 0 above;  gScale[r]=exp(diag_w)*rsqrt(sum u^2)
// ---------------------------------------------------------------------------
__global__ void __launch_bounds__(128) k_norm(const float* __restrict__ W,
                                              const float* __restrict__ diag_w) {
    const int r    = blockIdx.x;
    const int rb   = r >> 6;
    const int lo   = rb << 6;
    const int hi   = lo + 64;
    const int tid  = threadIdx.x;
    const int w    = tid >> 5;
    const int lane = tid & 31;

    float ss = 0.f;
    const int c0 = w * 128 + lane * 4;
    if (w * 128 < hi) {
        const float4 v = *(const float4*)(W + r * IN_F + c0);
        const float vv[4] = {v.x, v.y, v.z, v.w};
        #pragma unroll
        for (int j = 0; j < 4; j++) {
            const int c = c0 + j;
            float u;
            if (c >= hi)      u = 0.f;
            else if (c >= lo) u = __expf(vv[j]);
            else              u = vv[j];
            ss += u * u;
        }
    }
    #pragma unroll
    for (int off = 16; off > 0; off >>= 1)
        ss += __shfl_xor_sync(0xffffffffu, ss, off);
    __shared__ float sred[4];
    if (lane == 0) sred[w] = ss;
    __syncthreads();
    if (tid == 0) {
        const float wsn = sred[0] + sred[1] + sred[2] + sred[3];
        gScale[r] = __expf(diag_w[r]) * rsqrtf(wsn);
    }
}

// ---------------------------------------------------------------------------
// K2 fused, 256 threads:
//   bid <  36 : out partial tile (rt,kc), kc<=rt; w reconstructed inline
//   bid >= 36 : jac for (b,d) pair; As reconstructed inline from W + gScale
// ---------------------------------------------------------------------------
__global__ void __launch_bounds__(256) k_main(
        const float* __restrict__ grad,
        const float* __restrict__ W,
        const float* __restrict__ inputs,
        float* __restrict__ outp) {
    __shared__ float smemBuf[8768];
    const int bid = blockIdx.x;
    const int tid = threadIdx.x;

    if (bid >= 36) {
        // ---------------- jac: C = A^T @ exp(grad_b);  log ----------------
        const int jbid = bid - 36;       // = b*8 + d
        const int d    = jbid & 7;
        const int lo   = d << 6;
        float* As = smemBuf;             // [i][o]  64 x stride 68
        float* Bs = smemBuf + 64 * 68;   // [i][k]  64x64

        // Bs = exp(grad block)   (coalesced float4, DRAM)
        const float4* g4 = (const float4*)(grad + jbid * 4096);
        float4* Bs4 = (float4*)Bs;
        #pragma unroll
        for (int idx = tid; idx < 1024; idx += 256) {
            const float4 v = g4[idx];
            Bs4[idx] = make_float4(__expf(v.x), __expf(v.y), __expf(v.z), __expf(v.w));
        }
        // As[i][o] = gScale[lo+o] * exp(W[lo+o][lo+i])  (L2-resident W tile)
        #pragma unroll
        for (int m = 0; m < 4; m++) {
            const int idx = tid + 256 * m;
            const int o = idx >> 4, ig = idx & 15;
            const float sc = gScale[lo + o];
            const float4 v = *(const float4*)(W + (lo + o) * IN_F + lo + ig * 4);
            As[(ig * 4 + 0) * 68 + o] = sc * __expf(v.x);
            As[(ig * 4 + 1) * 68 + o] = sc * __expf(v.y);
            As[(ig * 4 + 2) * 68 + o] = sc * __expf(v.z);
            As[(ig * 4 + 3) * 68 + o] = sc * __expf(v.w);
        }
        __syncthreads();

        const int k_t = tid & 15;        // 16 x4 -> 64 k
        const int o_t = tid >> 4;        // 16 x4 -> 64 o
        float acc[4][4] = {};
        const float* ap = As + o_t * 4;
        const float* bp = Bs + k_t * 4;
        #pragma unroll 8
        for (int ii = 0; ii < 64; ii++) {
            const float4 a  = *(const float4*)(ap + ii * 68);
            const float4 bv = *(const float4*)(bp + ii * 64);
            acc[0][0] += a.x * bv.x; acc[0][1] += a.x * bv.y; acc[0][2] += a.x * bv.z; acc[0][3] += a.x * bv.w;
            acc[1][0] += a.y * bv.x; acc[1][1] += a.y * bv.y; acc[1][2] += a.y * bv.z; acc[1][3] += a.y * bv.w;
            acc[2][0] += a.z * bv.x; acc[2][1] += a.z * bv.y; acc[2][2] += a.z * bv.z; acc[2][3] += a.z * bv.w;
            acc[3][0] += a.w * bv.x; acc[3][1] += a.w * bv.y; acc[3][2] += a.w * bv.z; acc[3][3] += a.w * bv.w;
        }

        float* jb = outp + 32768 + jbid * 4096;   // jac block [o][k]
        #pragma unroll
        for (int jo = 0; jo < 4; jo++) {
            const int o = o_t * 4 + jo;
            float4 v = make_float4(__logf(acc[jo][0]), __logf(acc[jo][1]),
                                   __logf(acc[jo][2]), __logf(acc[jo][3]));
            *(float4*)(jb + o * 64 + k_t * 4) = v;
        }
    } else {
        // ---------------- out partial: tile (rt,kc), kc <= rt ----------------
        const int rt = RT_[bid];
        const int kc = KC_[bid];
        const bool diag = (rt == kc);
        float* sWT  = smemBuf;              // [kk][r] 64x68
        float* sInT = smemBuf + 64 * 68;    // [kk][b] 64x68

        // W fill: coalesced LDG, scale (+exp on diag tile), transposed STS
        #pragma unroll
        for (int m = 0; m < 4; m++) {
            const int idx = tid + 256 * m;
            const int rr = idx >> 4, kq = (idx & 15) * 4;
            const float sc = gScale[rt * 64 + rr];
            float4 v = *(const float4*)(W + (rt * 64 + rr) * IN_F + kc * 64 + kq);
            if (diag) {
                v.x = __expf(v.x); v.y = __expf(v.y);
                v.z = __expf(v.z); v.w = __expf(v.w);
            }
            sWT[(kq + 0) * 68 + rr] = sc * v.x;
            sWT[(kq + 1) * 68 + rr] = sc * v.y;
            sWT[(kq + 2) * 68 + rr] = sc * v.z;
            sWT[(kq + 3) * 68 + rr] = sc * v.w;
        }
        // inputs fill: coalesced LDG, transposed STS
        #pragma unroll
        for (int m = 0; m < 4; m++) {
            const int idx = tid + 256 * m;
            const int b = idx >> 4, kq = (idx & 15) * 4;
            const float4 v = *(const float4*)(inputs + b * IN_F + kc * 64 + kq);
            sInT[(kq + 0) * 68 + b] = v.x;
            sInT[(kq + 1) * 68 + b] = v.y;
            sInT[(kq + 2) * 68 + b] = v.z;
            sInT[(kq + 3) * 68 + b] = v.w;
        }
        __syncthreads();

        const int b4 = (tid & 15) * 4;   // 16 -> 64 b
        const int r4 = (tid >> 4) * 4;   // 16 -> 64 r
        float acc[4][4] = {};            // [bi][ri]
        const float* ip = sInT + b4;
        const float* wp = sWT + r4;
        #pragma unroll 8
        for (int kk = 0; kk < 64; kk++) {
            const float4 iv = *(const float4*)(ip + kk * 68);
            const float4 wv = *(const float4*)(wp + kk * 68);
            acc[0][0] += iv.x * wv.x; acc[0][1] += iv.x * wv.y; acc[0][2] += iv.x * wv.z; acc[0][3] += iv.x * wv.w;
            acc[1][0] += iv.y * wv.x; acc[1][1] += iv.y * wv.y; acc[1][2] += iv.y * wv.z; acc[1][3] += iv.y * wv.w;
            acc[2][0] += iv.z * wv.x; acc[2][1] += iv.z * wv.y; acc[2][2] += iv.z * wv.z; acc[2][3] += iv.z * wv.w;
            acc[3][0] += iv.w * wv.x; acc[3][1] += iv.w * wv.y; acc[3][2] += iv.w * wv.z; acc[3][3] += iv.w * wv.w;
        }

        float* part = gPart + kc * (BATCH * OUT_F) + rt * 64;
        #pragma unroll
        for (int bi = 0; bi < 4; bi++) {
            float4 v = make_float4(acc[bi][0], acc[bi][1], acc[bi][2], acc[bi][3]);
            *(float4*)(part + (b4 + bi) * OUT_F + r4) = v;
        }
    }
}

// ---------------------------------------------------------------------------
// K3: reduce partials (kc <= rt only) + bias -> out (first 32768 floats)
// ---------------------------------------------------------------------------
__global__ void __launch_bounds__(256) k_reduce(const float* __restrict__ bias,
                                                float* __restrict__ outp) {
    const int t    = blockIdx.x * 256 + threadIdx.x;   // < 8192
    const int idx4 = t * 4;
    const int r    = idx4 & 511;
    const int rt   = r >> 6;
    float4 s = *(const float4*)(bias + r);
    for (int kc = 0; kc <= rt; kc++) {
        const float4 p = *(const float4*)(gPart + kc * (BATCH * OUT_F) + idx4);
        s.x += p.x; s.y += p.y; s.z += p.z; s.w += p.w;
    }
    *(float4*)(outp + idx4) = s;
}

// ---------------------------------------------------------------------------
// inputs: [0] inputs (64x512 f32), [1] grad (64x8x64x64 f32),
//         [2] W (512x512 f32), [3] diag_w (512 f32), [4] bias (512 f32)
// d_out:  out (64x512) followed by jac (64x8x64x64), f32
// ---------------------------------------------------------------------------
extern "C" void kernel_launch(void* const* d_in, const int* in_sizes, int n_in,
                              void* d_out, int out_size) {
    const float* inputs = (const float*)d_in[0];
    const float* grad   = (const float*)d_in[1];
    const float* W      = (const float*)d_in[2];
    const float* diag_w = (const float*)d_in[3];
    const float* bias   = (const float*)d_in[4];
    float* outp = (float*)d_out;

    k_norm<<<512, 128>>>(W, diag_w);
    k_main<<<36 + 512, 256>>>(grad, W, inputs, outp);
    k_reduce<<<32, 256>>>(bias, outp);
}